// round 1
// baseline (speedup 1.0000x reference)
#include <cuda_runtime.h>
#include <math.h>

#define BATCH 512
#define SEQT  200
#define HID   128
#define GATES 512   // 4H
#define EMB   128
#define MTOT  (BATCH*SEQT)   // 102400
#define RPB   8              // batch rows per LSTM block

// ---------------- static scratch (no allocations allowed) ----------------
__device__ float g_zx_fw[(size_t)MTOT * GATES];   // 209.7 MB
__device__ float g_zx_bw[(size_t)MTOT * GATES];   // 209.7 MB
__device__ float g_s0f[(size_t)MTOT * HID];       // 52.4 MB
__device__ float g_s0b[(size_t)MTOT * HID];
__device__ float g_s1f[(size_t)MTOT * HID];
__device__ float g_s1b[(size_t)MTOT * HID];

// ---------------- GEMM: C[m,n] = sum_k A[m,k] * Wm[k,n] + bias[n] ----------------
// A: [MTOT, 128], Wm: [128, 512], C: [MTOT, 512]. Tile 128x128, BK=32, 256 thr, 8x8/thread.
__global__ __launch_bounds__(256) void gemm_zx(
    const float* __restrict__ A, const float* __restrict__ Wm,
    const float* __restrict__ bias, float* __restrict__ C)
{
    __shared__ float As[32][128];   // transposed A tile: As[k][m]
    __shared__ float Bs[32][128];   // Bs[k][n]

    int tid = threadIdx.x;
    int tx = tid & 15;          // 0..15 -> n sub-tile
    int ty = tid >> 4;          // 0..15 -> m sub-tile
    size_t m0 = (size_t)blockIdx.y * 128;
    int n0 = blockIdx.x * 128;

    float acc[8][8];
#pragma unroll
    for (int i = 0; i < 8; i++)
#pragma unroll
        for (int j = 0; j < 8; j++) acc[i][j] = 0.f;

    for (int k0 = 0; k0 < EMB; k0 += 32) {
        // load A tile (128 rows x 32 k), store transposed
#pragma unroll
        for (int i = 0; i < 4; i++) {
            int idx = tid + i * 256;      // 0..1023
            int row = idx >> 3;           // 0..127
            int kq  = idx & 7;            // 0..7 (float4 index)
            float4 v = *(const float4*)&A[(m0 + row) * EMB + k0 + kq * 4];
            As[kq*4+0][row] = v.x; As[kq*4+1][row] = v.y;
            As[kq*4+2][row] = v.z; As[kq*4+3][row] = v.w;
        }
        // load B tile (32 k x 128 n)
#pragma unroll
        for (int i = 0; i < 4; i++) {
            int idx = tid + i * 256;
            int row = idx >> 5;           // 0..31
            int nq  = idx & 31;           // 0..31
            *(float4*)&Bs[row][nq*4] =
                *(const float4*)&Wm[(size_t)(k0 + row) * GATES + n0 + nq * 4];
        }
        __syncthreads();
#pragma unroll
        for (int kk = 0; kk < 32; kk++) {
            float4 a0 = *(const float4*)&As[kk][ty*8];
            float4 a1 = *(const float4*)&As[kk][ty*8+4];
            float4 b0 = *(const float4*)&Bs[kk][tx*8];
            float4 b1 = *(const float4*)&Bs[kk][tx*8+4];
            float av[8] = {a0.x,a0.y,a0.z,a0.w,a1.x,a1.y,a1.z,a1.w};
            float bv[8] = {b0.x,b0.y,b0.z,b0.w,b1.x,b1.y,b1.z,b1.w};
#pragma unroll
            for (int i = 0; i < 8; i++)
#pragma unroll
                for (int j = 0; j < 8; j++)
                    acc[i][j] = fmaf(av[i], bv[j], acc[i][j]);
        }
        __syncthreads();
    }

    // epilogue: + bias
    float bl[8];
#pragma unroll
    for (int j = 0; j < 8; j++) bl[j] = bias[n0 + tx*8 + j];
#pragma unroll
    for (int i = 0; i < 8; i++) {
        size_t m = m0 + ty*8 + i;
        float* crow = &C[m * GATES + n0 + tx*8];
        float4 o0, o1;
        o0.x = acc[i][0] + bl[0]; o0.y = acc[i][1] + bl[1];
        o0.z = acc[i][2] + bl[2]; o0.w = acc[i][3] + bl[3];
        o1.x = acc[i][4] + bl[4]; o1.y = acc[i][5] + bl[5];
        o1.z = acc[i][6] + bl[6]; o1.w = acc[i][7] + bl[7];
        ((float4*)crow)[0] = o0; ((float4*)crow)[1] = o1;
    }
}

// ---------------- LSTM recurrence ----------------
__device__ __forceinline__ float sigm(float x) { return 1.f / (1.f + __expf(-x)); }

// grid (64, 2): blockIdx.y = direction (0 fw, 1 bw), 8 batch rows/block, 512 threads.
// Thread n computes z column n for all 8 rows; update phase: thread handles
// (rows rp,rp+1, hidden unit j). h kept transposed in smem, c in registers.
__global__ __launch_bounds__(512) void lstm_dir(
    const float* __restrict__ zx_fw, const float* __restrict__ zx_bw,
    const float* __restrict__ U_fw,  const float* __restrict__ U_bw,
    float* __restrict__ out_fw, float* __restrict__ out_bw)
{
    const int dir = blockIdx.y;
    const float* __restrict__ zx = dir ? zx_bw : zx_fw;
    const float* __restrict__ U  = dir ? U_bw  : U_fw;
    float* __restrict__ out      = dir ? out_bw : out_fw;

    const int b0  = blockIdx.x * RPB;
    const int tid = threadIdx.x;

    __shared__ float h_s[HID][RPB];     // h transposed: h_s[k][r]
    __shared__ float zb[RPB][GATES];    // z exchange buffer

    for (int q = tid; q < HID * RPB; q += 512) ((float*)h_s)[q] = 0.f;
    float c0 = 0.f, c1 = 0.f;

    const int n  = tid;                 // gate column
    const int j  = tid & 127;           // hidden unit (update phase)
    const int rp = (tid >> 7) << 1;     // row pair base: 0,2,4,6

    __syncthreads();

    for (int s = 0; s < SEQT; s++) {
        const int t = dir ? (SEQT - 1 - s) : s;

        float acc[RPB];
        const float* zxp = zx + ((size_t)b0 * SEQT + t) * GATES + n;
#pragma unroll
        for (int r = 0; r < RPB; r++)
            acc[r] = zxp[(size_t)r * SEQT * GATES];

        const float* Up = U + n;
#pragma unroll 8
        for (int k = 0; k < HID; k++) {
            float u = Up[(size_t)k * GATES];
            float4 ha = *(const float4*)&h_s[k][0];
            float4 hb = *(const float4*)&h_s[k][4];
            acc[0] = fmaf(ha.x, u, acc[0]);
            acc[1] = fmaf(ha.y, u, acc[1]);
            acc[2] = fmaf(ha.z, u, acc[2]);
            acc[3] = fmaf(ha.w, u, acc[3]);
            acc[4] = fmaf(hb.x, u, acc[4]);
            acc[5] = fmaf(hb.y, u, acc[5]);
            acc[6] = fmaf(hb.z, u, acc[6]);
            acc[7] = fmaf(hb.w, u, acc[7]);
        }
#pragma unroll
        for (int r = 0; r < RPB; r++) zb[r][n] = acc[r];
        __syncthreads();

        // gate/update phase: rows rp and rp+1, unit j
        {
            float zi = zb[rp][j], zf = zb[rp][128 + j];
            float zg = zb[rp][256 + j], zo = zb[rp][384 + j];
            float ig = sigm(zi), fg = sigm(zf), gg = tanhf(zg), og = sigm(zo);
            c0 = fg * c0 + ig * gg;
            float h = og * tanhf(c0);
            h_s[j][rp] = h;
            out[((size_t)(b0 + rp) * SEQT + t) * HID + j] = h;
        }
        {
            float zi = zb[rp+1][j], zf = zb[rp+1][128 + j];
            float zg = zb[rp+1][256 + j], zo = zb[rp+1][384 + j];
            float ig = sigm(zi), fg = sigm(zf), gg = tanhf(zg), og = sigm(zo);
            c1 = fg * c1 + ig * gg;
            float h = og * tanhf(c1);
            h_s[j][rp+1] = h;
            out[((size_t)(b0 + rp + 1) * SEQT + t) * HID + j] = h;
        }
        __syncthreads();
    }
}

// ---------------- final combine: (s1f + s0f + s1b + s0b) / 2 ----------------
__global__ void combine(const float* __restrict__ a, const float* __restrict__ b,
                        const float* __restrict__ c, const float* __restrict__ d,
                        float* __restrict__ out, int n4)
{
    int i = blockIdx.x * blockDim.x + threadIdx.x;
    if (i < n4) {
        float4 va = ((const float4*)a)[i];
        float4 vb = ((const float4*)b)[i];
        float4 vc = ((const float4*)c)[i];
        float4 vd = ((const float4*)d)[i];
        float4 o;
        o.x = 0.5f * (va.x + vb.x + vc.x + vd.x);
        o.y = 0.5f * (va.y + vb.y + vc.y + vd.y);
        o.z = 0.5f * (va.z + vb.z + vc.z + vd.z);
        o.w = 0.5f * (va.w + vb.w + vc.w + vd.w);
        ((float4*)out)[i] = o;
    }
}

// ---------------- launch ----------------
extern "C" void kernel_launch(void* const* d_in, const int* in_sizes, int n_in,
                              void* d_out, int out_size)
{
    const float* x = (const float*)d_in[0];
    const float* W = (const float*)d_in[1];   // [2,2,128,512]
    const float* U = (const float*)d_in[2];   // [2,2,128,512]
    const float* b = (const float*)d_in[3];   // [2,2,512]

    float *zxf, *zxb, *s0f, *s0b, *s1f, *s1b;
    cudaGetSymbolAddress((void**)&zxf, g_zx_fw);
    cudaGetSymbolAddress((void**)&zxb, g_zx_bw);
    cudaGetSymbolAddress((void**)&s0f, g_s0f);
    cudaGetSymbolAddress((void**)&s0b, g_s0b);
    cudaGetSymbolAddress((void**)&s1f, g_s1f);
    cudaGetSymbolAddress((void**)&s1b, g_s1b);

    const size_t WSZ = (size_t)EMB * GATES;   // 65536
    const float* W00 = W;           const float* W01 = W + WSZ;
    const float* W10 = W + 2*WSZ;   const float* W11 = W + 3*WSZ;
    const float* U00 = U;           const float* U01 = U + WSZ;
    const float* U10 = U + 2*WSZ;   const float* U11 = U + 3*WSZ;
    const float* b00 = b;           const float* b01 = b + GATES;
    const float* b10 = b + 2*GATES; const float* b11 = b + 3*GATES;

    dim3 gg(GATES / 128, MTOT / 128);   // (4, 800)
    dim3 gb(256);
    dim3 lg(BATCH / RPB, 2);            // (64, 2)

    // layer 0
    gemm_zx<<<gg, gb>>>(x, W00, b00, zxf);
    gemm_zx<<<gg, gb>>>(x, W01, b01, zxb);
    lstm_dir<<<lg, 512>>>(zxf, zxb, U00, U01, s0f, s0b);

    // layer 1 (input = layer-0 outputs per direction)
    gemm_zx<<<gg, gb>>>(s0f, W10, b10, zxf);
    gemm_zx<<<gg, gb>>>(s0b, W11, b11, zxb);
    lstm_dir<<<lg, 512>>>(zxf, zxb, U10, U11, s1f, s1b);

    // residual (layer 1) + average of directions
    int n4 = MTOT * HID / 4;
    combine<<<(n4 + 255) / 256, 256>>>(s1f, s0f, s1b, s0b, (float*)d_out, n4);
}